// round 4
// baseline (speedup 1.0000x reference)
#include <cuda_runtime.h>

// StackMemory degenerate form:
//   out[0, t, 0, h] = softmax(x_t @ W^T + b)[0] * sigmoid(x_t @ D)   (all h)
//   out[0, t, d, h] = 0   for d >= 1
// Store-bandwidth bound. Block-level role split (R2 WIN structure):
//   blocks [0, NVBLK)     : value blocks, 1 warp per timestep (8 t / block)
//   blocks [NVBLK, ...)   : zero blocks, 2 timesteps each, streaming 256-bit
//                           st.global.cs.v8.f32 stores.

#define T_LEN 8192
#define HID   400
#define DEPTH 32
#define NTHREADS 256
#define NVBLK (T_LEN / 8)          // 1024 value blocks
#define TPZB  2                    // timesteps per zero block
#define NZBLK (T_LEN / TPZB)       // 4096 zero blocks
#define ROWVEC (HID / 4)           // 100 float4 per (t, d) row
#define TVEC  (DEPTH * HID / 4)    // 3200 float4 per t

__device__ __forceinline__ void stg256_zero_cs(float4* p) {
#if __CUDA_ARCH__ >= 1000
    asm volatile(
        "st.global.cs.v8.f32 [%0], {%1,%1,%1,%1,%1,%1,%1,%1};"
        :: "l"(p), "f"(0.0f) : "memory");
#else
    const float4 z = make_float4(0.f, 0.f, 0.f, 0.f);
    __stcs(p, z);
    __stcs(p + 1, z);
#endif
}

__global__ __launch_bounds__(NTHREADS)
void stackmem_kernel(const float4* __restrict__ x4,  // (T, 100)
                     const float4* __restrict__ W4,  // (3, 100)
                     const float*  __restrict__ b,   // (3,)
                     const float4* __restrict__ D4,  // (100,)
                     float4* __restrict__ out4)      // (T, 32, 100)
{
    const int bid = blockIdx.x;
    const int tid = threadIdx.x;

    if (bid >= NVBLK) {
        // ========== zero block: TPZB timesteps' d>=1 regions =============
        const int t0 = (bid - NVBLK) * TPZB;
        const int NV8 = (TVEC - ROWVEC) / 2;          // 1550 v8-stores per t
        #pragma unroll
        for (int tt = 0; tt < TPZB; tt++) {
            float4* o = out4 + (size_t)(t0 + tt) * TVEC + ROWVEC;
            // 1550 = 6*256 + 14 : 6 full unrolled iterations + remainder
            #pragma unroll 2
            for (int i = tid; i < NV8; i += NTHREADS) {
                stg256_zero_cs(o + 2 * i);
            }
        }
        return;
    }

    // ==================== value block: 1 warp per t ======================
    const int warp = tid >> 5;
    const int lane = tid & 31;
    const int t = bid * 8 + warp;

    const float4* xt = x4 + (size_t)t * ROWVEC;

    float s0 = 0.f, s1 = 0.f, s2 = 0.f, sd = 0.f;
    #pragma unroll
    for (int base = 0; base < ROWVEC; base += 32) {
        int i = base + lane;
        if (i < ROWVEC) {
            float4 xv = xt[i];
            float4 w0 = W4[i];
            float4 w1 = W4[ROWVEC + i];
            float4 w2 = W4[2 * ROWVEC + i];
            float4 dv = D4[i];
            s0 = fmaf(xv.x, w0.x, fmaf(xv.y, w0.y, fmaf(xv.z, w0.z, fmaf(xv.w, w0.w, s0))));
            s1 = fmaf(xv.x, w1.x, fmaf(xv.y, w1.y, fmaf(xv.z, w1.z, fmaf(xv.w, w1.w, s1))));
            s2 = fmaf(xv.x, w2.x, fmaf(xv.y, w2.y, fmaf(xv.z, w2.z, fmaf(xv.w, w2.w, s2))));
            sd = fmaf(xv.x, dv.x, fmaf(xv.y, dv.y, fmaf(xv.z, dv.z, fmaf(xv.w, dv.w, sd))));
        }
    }

    #pragma unroll
    for (int off = 16; off > 0; off >>= 1) {
        s0 += __shfl_down_sync(0xffffffffu, s0, off);
        s1 += __shfl_down_sync(0xffffffffu, s1, off);
        s2 += __shfl_down_sync(0xffffffffu, s2, off);
        sd += __shfl_down_sync(0xffffffffu, sd, off);
    }

    float val;
    if (lane == 0) {
        float l0 = s0 + b[0];
        float l1 = s1 + b[1];
        float l2 = s2 + b[2];
        float m  = fmaxf(l0, fmaxf(l1, l2));
        float e0 = __expf(l0 - m);
        float e1 = __expf(l1 - m);
        float e2 = __expf(l2 - m);
        float push = e0 / (e0 + e1 + e2);
        float pv   = 1.0f / (1.0f + __expf(-sd));
        val = push * pv;
    }
    val = __shfl_sync(0xffffffffu, val, 0);

    float4* o = out4 + (size_t)t * TVEC;    // d=0 row, 100 float4 = 50 v8
    const float4 v4 = make_float4(val, val, val, val);
    // 50 v8-stores, lanes 0..31 then 0..17
    #pragma unroll
    for (int i = lane; i < ROWVEC / 2; i += 32) {
#if __CUDA_ARCH__ >= 1000
        asm volatile(
            "st.global.cs.v8.f32 [%0], {%1,%1,%1,%1,%1,%1,%1,%1};"
            :: "l"(o + 2 * i), "f"(val) : "memory");
#else
        __stcs(o + 2 * i, v4);
        __stcs(o + 2 * i + 1, v4);
#endif
    }
}

extern "C" void kernel_launch(void* const* d_in, const int* in_sizes, int n_in,
                              void* d_out, int out_size) {
    const float4* x = (const float4*)d_in[0];  // hidden_state (1, 8192, 400)
    const float4* W = (const float4*)d_in[1];  // W_ap (3, 400)
    const float*  b = (const float*) d_in[2];  // b_ap (3,)
    const float4* D = (const float4*)d_in[3];  // D (1, 400)
    float4* out = (float4*)d_out;              // (1, 8192, 32, 400)

    stackmem_kernel<<<NVBLK + NZBLK, NTHREADS>>>(x, W, b, D, out);
}

// round 5
// speedup vs baseline: 1.0614x; 1.0614x over previous
#include <cuda_runtime.h>

// StackMemory degenerate form:
//   out[0, t, 0, h] = softmax(x_t @ W^T + b)[0] * sigmoid(x_t @ D)   (all h)
//   out[0, t, d, h] = 0   for d >= 1
// Store-bandwidth bound. R2-winning block-level role split:
//   blocks [0, NVBLK)          : value blocks, 1 warp per timestep (8 t / block)
//   blocks [NVBLK, NVBLK+T_LEN): zero blocks, one t each, streaming __stcs
// R4 change: __launch_bounds__(256, 8) caps regs at 32 -> 8 blocks/SM -> full
// 64-warp occupancy, more outstanding stores in flight.

#define T_LEN 8192
#define HID   400
#define DEPTH 32
#define NTHREADS 256
#define NVBLK (T_LEN / 8)          // 1024 value blocks, 8 warps each
#define ROWVEC (HID / 4)           // 100 float4 per (t, d) row
#define TVEC  (DEPTH * HID / 4)    // 3200 float4 per t

__global__ __launch_bounds__(NTHREADS, 8)
void stackmem_kernel(const float4* __restrict__ x4,  // (T, 100)
                     const float4* __restrict__ W4,  // (3, 100)
                     const float*  __restrict__ b,   // (3,)
                     const float4* __restrict__ D4,  // (100,)
                     float4* __restrict__ out4)      // (T, 32, 100)
{
    const int bid = blockIdx.x;
    const int tid = threadIdx.x;

    if (bid >= NVBLK) {
        // ================= zero block: one timestep's d>=1 region ========
        const int t = bid - NVBLK;
        float4* o = out4 + (size_t)t * TVEC + ROWVEC;   // skip d=0 row
        const float4 z = make_float4(0.f, 0.f, 0.f, 0.f);
        const int N = TVEC - ROWVEC;                    // 3100
        #pragma unroll 4
        for (int i = tid; i < N; i += NTHREADS) {
            __stcs(o + i, z);
        }
        return;
    }

    // ==================== value block: 1 warp per t ======================
    const int warp = tid >> 5;
    const int lane = tid & 31;
    const int t = bid * 8 + warp;

    const float4* xt = x4 + (size_t)t * ROWVEC;

    float s0 = 0.f, s1 = 0.f, s2 = 0.f, sd = 0.f;
    #pragma unroll
    for (int base = 0; base < ROWVEC; base += 32) {
        int i = base + lane;
        if (i < ROWVEC) {
            float4 xv = xt[i];
            float4 w0 = W4[i];
            float4 w1 = W4[ROWVEC + i];
            float4 w2 = W4[2 * ROWVEC + i];
            float4 dv = D4[i];
            s0 = fmaf(xv.x, w0.x, fmaf(xv.y, w0.y, fmaf(xv.z, w0.z, fmaf(xv.w, w0.w, s0))));
            s1 = fmaf(xv.x, w1.x, fmaf(xv.y, w1.y, fmaf(xv.z, w1.z, fmaf(xv.w, w1.w, s1))));
            s2 = fmaf(xv.x, w2.x, fmaf(xv.y, w2.y, fmaf(xv.z, w2.z, fmaf(xv.w, w2.w, s2))));
            sd = fmaf(xv.x, dv.x, fmaf(xv.y, dv.y, fmaf(xv.z, dv.z, fmaf(xv.w, dv.w, sd))));
        }
    }

    #pragma unroll
    for (int off = 16; off > 0; off >>= 1) {
        s0 += __shfl_down_sync(0xffffffffu, s0, off);
        s1 += __shfl_down_sync(0xffffffffu, s1, off);
        s2 += __shfl_down_sync(0xffffffffu, s2, off);
        sd += __shfl_down_sync(0xffffffffu, sd, off);
    }

    float val;
    if (lane == 0) {
        float l0 = s0 + b[0];
        float l1 = s1 + b[1];
        float l2 = s2 + b[2];
        float m  = fmaxf(l0, fmaxf(l1, l2));
        float e0 = __expf(l0 - m);
        float e1 = __expf(l1 - m);
        float e2 = __expf(l2 - m);
        float push = e0 / (e0 + e1 + e2);
        float pv   = 1.0f / (1.0f + __expf(-sd));
        val = push * pv;
    }
    val = __shfl_sync(0xffffffffu, val, 0);

    const float4 v4 = make_float4(val, val, val, val);
    float4* o = out4 + (size_t)t * TVEC;    // d=0 row
    #pragma unroll
    for (int base = 0; base < ROWVEC; base += 32) {
        int i = base + lane;
        if (i < ROWVEC) __stcs(o + i, v4);
    }
}

extern "C" void kernel_launch(void* const* d_in, const int* in_sizes, int n_in,
                              void* d_out, int out_size) {
    const float4* x = (const float4*)d_in[0];  // hidden_state (1, 8192, 400)
    const float4* W = (const float4*)d_in[1];  // W_ap (3, 400)
    const float*  b = (const float*) d_in[2];  // b_ap (3,)
    const float4* D = (const float4*)d_in[3];  // D (1, 400)
    float4* out = (float4*)d_out;              // (1, 8192, 32, 400)

    stackmem_kernel<<<NVBLK + T_LEN, NTHREADS>>>(x, W, b, D, out);
}